// round 13
// baseline (speedup 1.0000x reference)
#include <cuda_runtime.h>

// GraphPyramidPooling — adjacency (d_in[0]) is dead code. Live math:
//   s0 = sig(h·w0+b0); s1 = sig(s0*(h·w1)+b1); s2 = sig((s0*s1)*(h·w2)+b2)
//   out[r] = a0[r]*h[r] + g1[r]*h[src1[r]] + g2[r]*h[src2[r]]
//
// R12: 3 launches. All ranks in ORIGINAL row indexing:
//   k0 = (s0bits<<32 | ~i)  (unique)
//   level-1 order among {k0>=T0}: lex(s1, k0) desc
//   level-2 selection among mask1: lex(s2, s1, k0) >= T2
// One kernel stages k0+s1 (48KB), computes T0/T1/T2 by exact MSD radix
// selects (2-stage lex fallback on ties), then one fused scan counts
// rank0 + masked rank1 per row and scatters everything the gather needs.

typedef unsigned long long u64;
typedef unsigned int u32;

#define D   512
#define DV  128
#define N0  4096
#define KS0 3276
#define KS1 1965
#define KS2 786

#define MNB 128
#define MNT 1024
#define SMEM_BYTES (N0 * 8 + N0 * 4)   // 49152

__device__ u64   g_k0[N0];
__device__ u32   g_s1b[N0];
__device__ u32   g_s2b[N0];
__device__ float g_a0[N0];
__device__ float g_g1[KS0];
__device__ int   g_src1[KS0];
__device__ float g_gain2[KS1];
__device__ int   g_src2[KS1];

__device__ __forceinline__ float warp_sum(float v) {
#pragma unroll
    for (int o = 16; o; o >>= 1) v += __shfl_xor_sync(0xffffffffu, v, o);
    return v;
}
__device__ __forceinline__ float sigmoidf(float x) {
    return 1.0f / (1.0f + expf(-x));
}

// K1: one warp per row; 3 dots; all three per-row scores (verified R10/R11).
__global__ void pass_a(const float* __restrict__ h,
                       const float* __restrict__ W,
                       const float* __restrict__ b) {
    int w    = (blockIdx.x * blockDim.x + threadIdx.x) >> 5;
    int lane = threadIdx.x & 31;
    if (w >= N0) return;
    const float4* hr = (const float4*)h + (size_t)w * DV;
    const float4* w0 = (const float4*)W;
    const float4* w1 = w0 + DV;
    const float4* w2 = w0 + 2 * DV;
    float a0 = 0.f, a1 = 0.f, a2 = 0.f;
#pragma unroll
    for (int i = 0; i < 4; i++) {
        float4 a  = __ldg(hr + lane + 32 * i);
        float4 c0 = __ldg(w0 + lane + 32 * i);
        float4 c1 = __ldg(w1 + lane + 32 * i);
        float4 c2 = __ldg(w2 + lane + 32 * i);
        a0 += a.x * c0.x + a.y * c0.y + a.z * c0.z + a.w * c0.w;
        a1 += a.x * c1.x + a.y * c1.y + a.z * c1.z + a.w * c1.w;
        a2 += a.x * c2.x + a.y * c2.y + a.z * c2.z + a.w * c2.w;
    }
    a0 = warp_sum(a0); a1 = warp_sum(a1); a2 = warp_sum(a2);
    if (lane == 0) {
        float s0 = sigmoidf(a0 + b[0]);
        float s1 = sigmoidf(s0 * a1 + b[1]);
        float s2 = sigmoidf((s0 * s1) * a2 + b[2]);
        g_k0[w]  = ((u64)(u32)__float_as_int(s0) << 32) | (u32)(~(u32)w);
        g_s1b[w] = (u32)__float_as_int(s1);
        g_s2b[w] = (u32)__float_as_int(s2);
    }
}

// Exact MSD radix select over a masked key set (functor f(j,&k) -> valid).
// Returns the threshold ROW index if a unique candidate is isolated (always
// happens for unique key sets); otherwise returns -1 with out_prefix = the
// duplicated full key value and out_res = residual want within that group.
template <class F>
__device__ int radix_sel(F f, int n, int want0, u32* hist, int* ctl, int* s_j,
                         u64& out_prefix, int& out_res) {
    const int tid = threadIdx.x;
    int want = want0;
    u64 prefix = 0, pmask = 0;
    for (int shift = 56; shift >= 0; shift -= 8) {
        if (tid < 256) hist[tid] = 0;
        __syncthreads();
        for (int j = tid; j < n; j += MNT) {
            u64 k;
            if (f(j, k) && ((k ^ prefix) & pmask) == 0)
                atomicAdd(&hist[(u32)(k >> shift) & 255], 1u);
        }
        __syncthreads();
        if (tid < 32) {
            u32 hh[8]; u32 lsum = 0;
#pragma unroll
            for (int q = 0; q < 8; q++) { hh[q] = hist[tid * 8 + q]; lsum += hh[q]; }
            u32 suf = lsum;   // inclusive suffix over lanes (hi lane = hi digit)
#pragma unroll
            for (int o = 1; o < 32; o <<= 1) {
                u32 v = __shfl_down_sync(0xffffffffu, suf, o);
                if (tid + o < 32) suf += v;
            }
            u32 run = suf - lsum;   // keys with digit strictly above this lane
            for (int q = 7; q >= 0; q--) {
                u32 ge = run + hh[q];
                if ((int)run < want && want <= (int)ge) {
                    ctl[0] = tid * 8 + q;
                    ctl[1] = want - (int)run;
                    ctl[2] = (int)hh[q];
                }
                run = ge;
            }
        }
        __syncthreads();
        const int bin = ctl[0];
        const int cnt = ctl[2];
        want = ctl[1];
        prefix |= ((u64)(u32)bin) << shift;
        pmask  |= 255ULL << shift;
        __syncthreads();
        if (cnt == 1) {
            for (int j = tid; j < n; j += MNT) {
                u64 k;
                if (f(j, k) && ((k ^ prefix) & pmask) == 0) *s_j = j;
            }
            __syncthreads();
            return *s_j;
        }
    }
    out_prefix = prefix;
    out_res = want;
    return -1;
}

// K2: thresholds + fused rank0/rank1 scan + scatter. 128 blocks x 1024 thr,
// one warp per row (block owns rows [blockIdx*32, blockIdx*32+32)).
__global__ void __launch_bounds__(MNT) megarank() {
    extern __shared__ __align__(16) u64 sh[];
    u64* K0s = sh;                 // 4096 u64 (32KB)
    u32* S1s = (u32*)(sh + N0);    // 4096 u32 (16KB)
    __shared__ u32 hist[256];
    __shared__ int ctl[3];
    __shared__ int s_j;

    const int tid = threadIdx.x;
    for (int t = tid; t < N0 / 2; t += MNT)
        ((ulonglong2*)K0s)[t] = __ldg((const ulonglong2*)g_k0 + t);
    for (int t = tid; t < N0 / 4; t += MNT)
        ((uint4*)S1s)[t] = __ldg((const uint4*)g_s1b + t);
    __syncthreads();

    u64 dp; int dr;

    // ---- T0: KS0-th largest k0 (unique -> exact) ----
    auto f0 = [&](int j, u64& k) { k = K0s[j]; return true; };
    const int j0 = radix_sel(f0, N0, KS0, hist, ctl, &s_j, dp, dr);
    const u64 T0 = K0s[j0];

    // ---- T1: KS1-th largest lex(s1, k0) among {k0 >= T0} ----
    auto f1a = [&](int j, u64& k) {
        u64 kk = K0s[j];
        if (kk < T0) return false;
        k = ((u64)S1s[j] << 32) | (kk >> 32);   // (s1, s0)
        return true;
    };
    u64 p1 = 0; int w1 = 0;
    int j1 = radix_sel(f1a, N0, KS1, hist, ctl, &s_j, p1, w1);
    if (j1 < 0) {   // (s1,s0) duplicates: break by ~i (low 32 of k0, unique)
        auto f1b = [&](int j, u64& k) {
            u64 kk = K0s[j];
            if (kk < T0) return false;
            if (((((u64)S1s[j]) << 32) | (kk >> 32)) != p1) return false;
            k = (u64)(u32)kk;
            return true;
        };
        j1 = radix_sel(f1b, N0, w1, hist, ctl, &s_j, dp, dr);
    }
    const u32 T1s1 = S1s[j1];
    const u64 T1k0 = K0s[j1];

    // ---- T2: KS2-th largest lex(s2, s1, k0) among mask1 ----
    auto m1f = [&](int j) {
        u64 kk = K0s[j];
        if (kk < T0) return false;
        u32 s1 = S1s[j];
        return (s1 > T1s1) || (s1 == T1s1 && kk >= T1k0);
    };
    auto f2a = [&](int j, u64& k) {
        if (!m1f(j)) return false;
        k = ((u64)__ldg(g_s2b + j) << 32) | S1s[j];   // (s2, s1)
        return true;
    };
    u64 p2 = 0; int w2 = 0;
    int j2 = radix_sel(f2a, N0, KS2, hist, ctl, &s_j, p2, w2);
    if (j2 < 0) {   // (s2,s1) duplicates: break by full k0 (unique)
        auto f2b = [&](int j, u64& k) {
            if (!m1f(j)) return false;
            if ((((u64)__ldg(g_s2b + j) << 32) | S1s[j]) != p2) return false;
            k = K0s[j];
            return true;
        };
        j2 = radix_sel(f2b, N0, w2, hist, ctl, &s_j, dp, dr);
    }
    const u32 T2s2 = __ldg(g_s2b + j2);
    const u32 T2s1 = S1s[j2];
    const u64 T2k0 = K0s[j2];

    // ---- fused scan: rank0 (k0 desc) + rank1 (lex(s1,k0) desc among m0) ----
    const int wid  = tid >> 5;
    const int lane = tid & 31;
    const int i = blockIdx.x * 32 + wid;   // 128*32 = 4096, always < N0
    const u64 kI = K0s[i];
    const u32 sI = S1s[i];
    int c0 = 0, c1 = 0;
    const ulonglong2* K2p = (const ulonglong2*)K0s;
    const uint2*      S2q = (const uint2*)S1s;
#pragma unroll 4
    for (int q = lane; q < N0 / 2; q += 32) {
        ulonglong2 kv = K2p[q];
        uint2      sv = S2q[q];
        int g0x = (int)(kv.x > kI), g0y = (int)(kv.y > kI);
        int l1x = (int)(sv.x > sI) | ((int)(sv.x == sI) & g0x);
        int l1y = (int)(sv.y > sI) | ((int)(sv.y == sI) & g0y);
        c0 += g0x + g0y;
        c1 += ((int)(kv.x >= T0) & l1x) + ((int)(kv.y >= T0) & l1y);
    }
    int p = c0 | (c1 << 16);
#pragma unroll
    for (int o = 16; o; o >>= 1) p += __shfl_xor_sync(0xffffffffu, p, o);

    if (lane == 0) {
        const int rank0 = p & 0xFFFF;
        const int rank1 = p >> 16;
        const float s0 = __uint_as_float((int)(u32)(kI >> 32));
        const bool sel0 = kI >= T0;           // == (rank0 < KS0), exact
        g_a0[i] = sel0 ? s0 : 0.f;
        if (sel0) {
            const float s1 = __uint_as_float((int)sI);
            const float gain1 = s0 * s1;
            const bool m1i = (sI > T1s1) || (sI == T1s1 && kI >= T1k0);
            g_g1[rank0]   = m1i ? gain1 : 0.f;
            g_src1[rank0] = i;
            if (m1i) {
                const u32 s2b = __ldg(g_s2b + i);
                const bool sel2 = (s2b > T2s2) ||
                    (s2b == T2s2 && (sI > T2s1 ||
                                     (sI == T2s1 && kI >= T2k0)));
                g_gain2[rank1] = sel2 ? gain1 * __uint_as_float((int)s2b) : 0.f;
                g_src2[rank1]  = i;
            }
        }
    }
}

// K3: out[r] = a0*h[r] + g1*h[src1] + g2*h[src2] (verified R10 gather).
__global__ void __launch_bounds__(512)
final_kernel(const float* __restrict__ h, float* __restrict__ out) {
    int tid = blockIdx.x * 512 + threadIdx.x;   // 0 .. N0*DV-1
    int r = tid >> 7;
    int c = tid & 127;
    const float4* h4 = (const float4*)h;
    float a0 = __ldg(g_a0 + r);
    float4 v0 = __ldg(h4 + (size_t)r * DV + c);
    float4 o;
    o.x = a0 * v0.x; o.y = a0 * v0.y; o.z = a0 * v0.z; o.w = a0 * v0.w;
    if (r < KS0) {
        float g1 = __ldg(g_g1 + r);
        int   s1 = __ldg(g_src1 + r);
        float4 v1 = __ldg(h4 + (size_t)s1 * DV + c);
        o.x += g1 * v1.x; o.y += g1 * v1.y; o.z += g1 * v1.z; o.w += g1 * v1.w;
        if (r < KS1) {
            float g2 = __ldg(g_gain2 + r);
            int   s2 = __ldg(g_src2 + r);
            float4 v2 = __ldg(h4 + (size_t)s2 * DV + c);
            o.x += g2 * v2.x; o.y += g2 * v2.y; o.z += g2 * v2.z; o.w += g2 * v2.w;
        }
    }
    ((float4*)out)[tid] = o;
}

extern "C" void kernel_launch(void* const* d_in, const int* in_sizes, int n_in,
                              void* d_out, int out_size) {
    // inputs: [0]=g (UNUSED), [1]=h [4096,512], [2]=W [3,512], [3]=b [3]
    const float* h = (const float*)d_in[1];
    const float* W = (const float*)d_in[2];
    const float* b = (const float*)d_in[3];
    float* out = (float*)d_out;

    cudaFuncSetAttribute(megarank,
                         cudaFuncAttributeMaxDynamicSharedMemorySize,
                         SMEM_BYTES);
    pass_a<<<N0 / 8, 256>>>(h, W, b);
    megarank<<<MNB, MNT, SMEM_BYTES>>>();
    final_kernel<<<(N0 * DV) / 512, 512>>>(h, out);
}